// round 1
// baseline (speedup 1.0000x reference)
#include <cuda_runtime.h>
#include <math.h>

// ---------------------------------------------------------------------------
// Problem constants
// ---------------------------------------------------------------------------
constexpr int Bb   = 8;
constexpr int Tt   = 1024;
constexpr int Cc   = 768;
constexpr int NHh  = 12;
constexpr int HSz  = 64;
constexpr int MR   = Bb * Tt;      // 8192 rows
constexpr int FFd  = 4 * Cc;       // 3072

// ---------------------------------------------------------------------------
// Scratch (device globals; no cudaMalloc allowed)
// ---------------------------------------------------------------------------
__device__ float g_h [(size_t)MR * Cc];
__device__ float g_q [(size_t)MR * Cc];
__device__ float g_k [(size_t)MR * Cc];
__device__ float g_v [(size_t)MR * Cc];
__device__ float g_o [(size_t)MR * Cc];
__device__ float g_x2[(size_t)MR * Cc];
__device__ float g_h2[(size_t)MR * Cc];
__device__ float g_ff[(size_t)MR * FFd];

// ---------------------------------------------------------------------------
// LayerNorm: one block (256 threads) per row of 768
// ---------------------------------------------------------------------------
__device__ __forceinline__ float block_sum(float v, float* red) {
    #pragma unroll
    for (int o = 16; o > 0; o >>= 1) v += __shfl_xor_sync(0xffffffffu, v, o);
    int w = threadIdx.x >> 5;
    if ((threadIdx.x & 31) == 0) red[w] = v;
    __syncthreads();
    if (threadIdx.x == 0) {
        float t = 0.f;
        #pragma unroll
        for (int i = 0; i < 8; i++) t += red[i];
        red[0] = t;
    }
    __syncthreads();
    float r = red[0];
    __syncthreads();   // allow red[] reuse
    return r;
}

__global__ __launch_bounds__(256) void ln_kernel(
    const float* __restrict__ X, const float* __restrict__ g,
    const float* __restrict__ be, float* __restrict__ Y)
{
    __shared__ float red[8];
    int row = blockIdx.x, tid = threadIdx.x;
    const float* x = X + (size_t)row * Cc;
    float v0 = x[tid], v1 = x[tid + 256], v2 = x[tid + 512];
    float s  = block_sum(v0 + v1 + v2, red);
    float mu = s * (1.0f / Cc);
    float d0 = v0 - mu, d1 = v1 - mu, d2 = v2 - mu;
    float sq = block_sum(d0 * d0 + d1 * d1 + d2 * d2, red);
    float inv = rsqrtf(sq * (1.0f / Cc) + 1e-5f);
    float* y = Y + (size_t)row * Cc;
    y[tid]       = d0 * inv * g[tid]       + be[tid];
    y[tid + 256] = d1 * inv * g[tid + 256] + be[tid + 256];
    y[tid + 512] = d2 * inv * g[tid + 512] + be[tid + 512];
}

// ---------------------------------------------------------------------------
// SGEMM: C[M,N] = A[M,K] @ B[K,N] (row-major), 128x128x16 tiles,
// 256 threads, 8x8 register tile per thread.
// EP: 0 = plain, 1 = resid + acc + bias, 2 = gelu(acc + bias)
// All shapes used are exact multiples of the tile sizes.
// ---------------------------------------------------------------------------
template<int EP>
__global__ __launch_bounds__(256) void sgemm(
    const float* __restrict__ A, const float* __restrict__ Bm,
    const float* __restrict__ bias, const float* __restrict__ resid,
    float* __restrict__ Cm, int M, int N, int K)
{
    constexpr int BM = 128, BN = 128, BK = 16;
    __shared__ float As[BK][BM];   // stored transposed (k-major)
    __shared__ float Bs[BK][BN];

    int tid = threadIdx.x;
    int bm  = blockIdx.y * BM;
    int bn  = blockIdx.x * BN;
    int tx  = tid & 15;            // 0..15
    int ty  = tid >> 4;            // 0..15

    const float* Ag = A  + (size_t)bm * K;
    const float* Bg = Bm + bn;

    float acc[8][8];
    #pragma unroll
    for (int i = 0; i < 8; i++)
        #pragma unroll
        for (int j = 0; j < 8; j++) acc[i][j] = 0.f;

    for (int k0 = 0; k0 < K; k0 += BK) {
        // --- load A tile (128 x 16) transposed into As ---
        #pragma unroll
        for (int i = 0; i < 2; i++) {
            int idx = tid + i * 256;           // 0..511 float4s
            int r   = idx >> 2;                // 0..127
            int c4  = (idx & 3) << 2;          // 0,4,8,12
            float4 vv = *(const float4*)(Ag + (size_t)r * K + k0 + c4);
            As[c4 + 0][r] = vv.x;
            As[c4 + 1][r] = vv.y;
            As[c4 + 2][r] = vv.z;
            As[c4 + 3][r] = vv.w;
        }
        // --- load B tile (16 x 128) ---
        #pragma unroll
        for (int i = 0; i < 2; i++) {
            int idx = tid + i * 256;           // 0..511 float4s
            int r   = idx >> 5;                // 0..15
            int c4  = (idx & 31) << 2;         // 0..124
            *(float4*)(&Bs[r][c4]) = *(const float4*)(Bg + (size_t)(k0 + r) * N + c4);
        }
        __syncthreads();

        #pragma unroll
        for (int kk = 0; kk < BK; kk++) {
            float a[8], b[8];
            *(float4*)(a)     = *(const float4*)(&As[kk][ty * 8]);
            *(float4*)(a + 4) = *(const float4*)(&As[kk][ty * 8 + 4]);
            *(float4*)(b)     = *(const float4*)(&Bs[kk][tx * 8]);
            *(float4*)(b + 4) = *(const float4*)(&Bs[kk][tx * 8 + 4]);
            #pragma unroll
            for (int i = 0; i < 8; i++)
                #pragma unroll
                for (int j = 0; j < 8; j++)
                    acc[i][j] = fmaf(a[i], b[j], acc[i][j]);
        }
        __syncthreads();
    }

    // --- epilogue ---
    int colb = bn + tx * 8;
    float bv[8];
    if (EP != 0) {
        *(float4*)(bv)     = *(const float4*)(bias + colb);
        *(float4*)(bv + 4) = *(const float4*)(bias + colb + 4);
    }
    #pragma unroll
    for (int i = 0; i < 8; i++) {
        int row = bm + ty * 8 + i;
        float out[8];
        #pragma unroll
        for (int j = 0; j < 8; j++) {
            float v = acc[i][j];
            if (EP == 1) v += bv[j];
            if (EP == 2) {
                v += bv[j];
                v = 0.5f * v * (1.0f + erff(v * 0.70710678118654752f));
            }
            out[j] = v;
        }
        if (EP == 1) {
            float4 r0 = *(const float4*)(resid + (size_t)row * N + colb);
            float4 r1 = *(const float4*)(resid + (size_t)row * N + colb + 4);
            out[0] += r0.x; out[1] += r0.y; out[2] += r0.z; out[3] += r0.w;
            out[4] += r1.x; out[5] += r1.y; out[6] += r1.z; out[7] += r1.w;
        }
        *(float4*)(Cm + (size_t)row * N + colb)     = *(float4*)(out);
        *(float4*)(Cm + (size_t)row * N + colb + 4) = *(float4*)(out + 4);
    }
}

// ---------------------------------------------------------------------------
// Causal flash attention, fp32. One CTA = 64 query rows of one (b,h).
// 256 threads: tr = tid/16 (0..15), tc = tid%16. Each thread owns a 4x4
// tile of both S (rows 4tr.., cols 4tc..) and O (rows 4tr.., dims 4tc..).
// Online softmax state (m,l) kept redundantly in registers of all 16
// threads sharing tr (identical by shfl reduction -> no smem races).
// ---------------------------------------------------------------------------
constexpr int ATTN_SMEM_FLOATS = 64 * 65 + 64 * 64 + 64 * 64 + 64 * 65;
constexpr int ATTN_SMEM_BYTES  = ATTN_SMEM_FLOATS * 4;   // 66048

__global__ __launch_bounds__(256) void attn_kernel(
    const float* __restrict__ Q, const float* __restrict__ K,
    const float* __restrict__ V, float* __restrict__ O)
{
    extern __shared__ float sm[];
    float* sQ  = sm;                    // [64][65]
    float* sKt = sQ  + 64 * 65;         // [64(d)][64(j)]
    float* sV  = sKt + 64 * 64;         // [64(j)][64(d)]
    float* sP  = sV  + 64 * 64;         // [64][65]

    int tid = threadIdx.x;
    int ib  = blockIdx.x;               // query block index (0..15)
    int bh  = blockIdx.y;               // b*NH + h
    int b   = bh / NHh, h = bh % NHh;
    const size_t base = (size_t)b * Tt * Cc + (size_t)h * HSz;

    int tc = tid & 15, tr = tid >> 4;

    // load Q tile
    #pragma unroll
    for (int i = 0; i < 16; i++) {
        int idx = tid + i * 256;        // 0..4095
        int r = idx >> 6, d = idx & 63;
        sQ[r * 65 + d] = Q[base + (size_t)(ib * 64 + r) * Cc + d];
    }

    float m[4], l[4], o[4][4];
    #pragma unroll
    for (int rr = 0; rr < 4; rr++) {
        m[rr] = -INFINITY; l[rr] = 0.f;
        #pragma unroll
        for (int cc = 0; cc < 4; cc++) o[rr][cc] = 0.f;
    }
    const float scale = 0.03608439182435161f;   // 768^-0.5 (note: C, not hs)

    for (int jb = 0; jb <= ib; jb++) {
        __syncthreads();  // protects sQ (iter 0) and prior sKt/sV/sP reads
        // load K (transposed) and V tiles
        #pragma unroll
        for (int i = 0; i < 16; i++) {
            int idx = tid + i * 256;
            int r = idx >> 6, d = idx & 63;
            float kv = K[base + (size_t)(jb * 64 + r) * Cc + d];
            float vv = V[base + (size_t)(jb * 64 + r) * Cc + d];
            sKt[d * 64 + r] = kv;
            sV [r * 64 + d] = vv;
        }
        __syncthreads();

        // S = Q K^T (4x4 per thread)
        float s[4][4];
        #pragma unroll
        for (int rr = 0; rr < 4; rr++)
            #pragma unroll
            for (int cc = 0; cc < 4; cc++) s[rr][cc] = 0.f;

        #pragma unroll 4
        for (int d = 0; d < 64; d++) {
            float a0 = sQ[(tr * 4 + 0) * 65 + d];
            float a1 = sQ[(tr * 4 + 1) * 65 + d];
            float a2 = sQ[(tr * 4 + 2) * 65 + d];
            float a3 = sQ[(tr * 4 + 3) * 65 + d];
            float4 bb = *(const float4*)(&sKt[d * 64 + tc * 4]);
            s[0][0] = fmaf(a0, bb.x, s[0][0]); s[0][1] = fmaf(a0, bb.y, s[0][1]);
            s[0][2] = fmaf(a0, bb.z, s[0][2]); s[0][3] = fmaf(a0, bb.w, s[0][3]);
            s[1][0] = fmaf(a1, bb.x, s[1][0]); s[1][1] = fmaf(a1, bb.y, s[1][1]);
            s[1][2] = fmaf(a1, bb.z, s[1][2]); s[1][3] = fmaf(a1, bb.w, s[1][3]);
            s[2][0] = fmaf(a2, bb.x, s[2][0]); s[2][1] = fmaf(a2, bb.y, s[2][1]);
            s[2][2] = fmaf(a2, bb.z, s[2][2]); s[2][3] = fmaf(a2, bb.w, s[2][3]);
            s[3][0] = fmaf(a3, bb.x, s[3][0]); s[3][1] = fmaf(a3, bb.y, s[3][1]);
            s[3][2] = fmaf(a3, bb.z, s[3][2]); s[3][3] = fmaf(a3, bb.w, s[3][3]);
        }

        int irow0 = ib * 64 + tr * 4;
        int jcol0 = jb * 64 + tc * 4;
        #pragma unroll
        for (int rr = 0; rr < 4; rr++)
            #pragma unroll
            for (int cc = 0; cc < 4; cc++) {
                float v = s[rr][cc] * scale;
                s[rr][cc] = (jcol0 + cc > irow0 + rr) ? -INFINITY : v;
            }

        // online softmax per row (redundant across 16 threads of a row group)
        #pragma unroll
        for (int rr = 0; rr < 4; rr++) {
            float bmax = fmaxf(fmaxf(s[rr][0], s[rr][1]), fmaxf(s[rr][2], s[rr][3]));
            #pragma unroll
            for (int off = 1; off < 16; off <<= 1)
                bmax = fmaxf(bmax, __shfl_xor_sync(0xffffffffu, bmax, off));
            float mn = fmaxf(m[rr], bmax);
            float sum = 0.f;
            #pragma unroll
            for (int cc = 0; cc < 4; cc++) {
                float p = __expf(s[rr][cc] - mn);
                s[rr][cc] = p;
                sum += p;
            }
            #pragma unroll
            for (int off = 1; off < 16; off <<= 1)
                sum += __shfl_xor_sync(0xffffffffu, sum, off);
            float alpha = __expf(m[rr] - mn);
            l[rr] = l[rr] * alpha + sum;
            m[rr] = mn;
            #pragma unroll
            for (int cc = 0; cc < 4; cc++) o[rr][cc] *= alpha;
            #pragma unroll
            for (int cc = 0; cc < 4; cc++)
                sP[(tr * 4 + rr) * 65 + tc * 4 + cc] = s[rr][cc];
        }
        __syncthreads();

        // O += P V  (4 rows x 4 dims per thread)
        #pragma unroll 4
        for (int j = 0; j < 64; j++) {
            float4 vv = *(const float4*)(&sV[j * 64 + tc * 4]);
            float p0 = sP[(tr * 4 + 0) * 65 + j];
            float p1 = sP[(tr * 4 + 1) * 65 + j];
            float p2 = sP[(tr * 4 + 2) * 65 + j];
            float p3 = sP[(tr * 4 + 3) * 65 + j];
            o[0][0] = fmaf(p0, vv.x, o[0][0]); o[0][1] = fmaf(p0, vv.y, o[0][1]);
            o[0][2] = fmaf(p0, vv.z, o[0][2]); o[0][3] = fmaf(p0, vv.w, o[0][3]);
            o[1][0] = fmaf(p1, vv.x, o[1][0]); o[1][1] = fmaf(p1, vv.y, o[1][1]);
            o[1][2] = fmaf(p1, vv.z, o[1][2]); o[1][3] = fmaf(p1, vv.w, o[1][3]);
            o[2][0] = fmaf(p2, vv.x, o[2][0]); o[2][1] = fmaf(p2, vv.y, o[2][1]);
            o[2][2] = fmaf(p2, vv.z, o[2][2]); o[2][3] = fmaf(p2, vv.w, o[2][3]);
            o[3][0] = fmaf(p3, vv.x, o[3][0]); o[3][1] = fmaf(p3, vv.y, o[3][1]);
            o[3][2] = fmaf(p3, vv.z, o[3][2]); o[3][3] = fmaf(p3, vv.w, o[3][3]);
        }
    }

    // write normalized output
    #pragma unroll
    for (int rr = 0; rr < 4; rr++) {
        float inv = 1.0f / l[rr];
        size_t orow = base + (size_t)(ib * 64 + tr * 4 + rr) * Cc + tc * 4;
        float4 ov;
        ov.x = o[rr][0] * inv; ov.y = o[rr][1] * inv;
        ov.z = o[rr][2] * inv; ov.w = o[rr][3] * inv;
        *(float4*)(&O[orow]) = ov;
    }
}

// ---------------------------------------------------------------------------
// Launch
// ---------------------------------------------------------------------------
extern "C" void kernel_launch(void* const* d_in, const int* in_sizes, int n_in,
                              void* d_out, int out_size)
{
    const float* x   = (const float*)d_in[0];
    const float* Wq  = (const float*)d_in[1];
    const float* Wk  = (const float*)d_in[2];
    const float* Wv  = (const float*)d_in[3];
    const float* Wo  = (const float*)d_in[4];
    const float* bo  = (const float*)d_in[5];
    const float* W1  = (const float*)d_in[6];
    const float* b1  = (const float*)d_in[7];
    const float* W2  = (const float*)d_in[8];
    const float* b2  = (const float*)d_in[9];
    const float* g1  = (const float*)d_in[10];
    const float* be1 = (const float*)d_in[11];
    const float* g2  = (const float*)d_in[12];
    const float* be2 = (const float*)d_in[13];
    float* out = (float*)d_out;

    float *h, *q, *k, *v, *o, *x2, *h2, *ff;
    cudaGetSymbolAddress((void**)&h,  g_h);
    cudaGetSymbolAddress((void**)&q,  g_q);
    cudaGetSymbolAddress((void**)&k,  g_k);
    cudaGetSymbolAddress((void**)&v,  g_v);
    cudaGetSymbolAddress((void**)&o,  g_o);
    cudaGetSymbolAddress((void**)&x2, g_x2);
    cudaGetSymbolAddress((void**)&h2, g_h2);
    cudaGetSymbolAddress((void**)&ff, g_ff);

    cudaFuncSetAttribute(attn_kernel,
                         cudaFuncAttributeMaxDynamicSharedMemorySize,
                         ATTN_SMEM_BYTES);

    dim3 blk(256);
    dim3 g768(Cc / 128, MR / 128);    // (6, 64)
    dim3 g3072(FFd / 128, MR / 128);  // (24, 64)

    // h = LN(x; g1, be1)
    ln_kernel<<<MR, blk>>>(x, g1, be1, h);
    // q/k/v = h @ W{q,k,v}
    sgemm<0><<<g768, blk>>>(h, Wq, nullptr, nullptr, q, MR, Cc, Cc);
    sgemm<0><<<g768, blk>>>(h, Wk, nullptr, nullptr, k, MR, Cc, Cc);
    sgemm<0><<<g768, blk>>>(h, Wv, nullptr, nullptr, v, MR, Cc, Cc);
    // causal attention
    attn_kernel<<<dim3(Tt / 64, Bb * NHh), blk, ATTN_SMEM_BYTES>>>(q, k, v, o);
    // x2 = x + o @ Wo + bo
    sgemm<1><<<g768, blk>>>(o, Wo, bo, x, x2, MR, Cc, Cc);
    // h2 = LN(x2; g2, be2)
    ln_kernel<<<MR, blk>>>(x2, g2, be2, h2);
    // ff = gelu(h2 @ W1 + b1)
    sgemm<2><<<g3072, blk>>>(h2, W1, b1, nullptr, ff, MR, FFd, Cc);
    // out = x2 + ff @ W2 + b2
    sgemm<1><<<g768, blk>>>(ff, W2, b2, x2, out, MR, Cc, FFd);
}

// round 3
// speedup vs baseline: 2.3112x; 2.3112x over previous
#include <cuda_runtime.h>
#include <math.h>
#include <stdint.h>

// ---------------------------------------------------------------------------
// Problem constants
// ---------------------------------------------------------------------------
constexpr int Bb   = 8;
constexpr int Tt   = 1024;
constexpr int Cc   = 768;
constexpr int NHh  = 12;
constexpr int HSz  = 64;
constexpr int MR   = Bb * Tt;      // 8192 rows
constexpr int FFd  = 4 * Cc;       // 3072

// ---------------------------------------------------------------------------
// Scratch (device globals; no cudaMalloc allowed)
// tf32 operands stored as uint32_t bit patterns.
// ---------------------------------------------------------------------------
__device__ uint32_t g_h [(size_t)MR * Cc];     // LN1 out (tf32)
__device__ float    g_q [(size_t)MR * Cc];
__device__ float    g_k [(size_t)MR * Cc];
__device__ float    g_v [(size_t)MR * Cc];
__device__ uint32_t g_o [(size_t)MR * Cc];     // attn out (tf32)
__device__ float    g_x2[(size_t)MR * Cc];
__device__ uint32_t g_h2[(size_t)MR * Cc];     // LN2 out (tf32)
__device__ uint32_t g_ff[(size_t)MR * FFd];    // gelu out (tf32)
__device__ uint32_t g_wq[(size_t)Cc * Cc];
__device__ uint32_t g_wk[(size_t)Cc * Cc];
__device__ uint32_t g_wv[(size_t)Cc * Cc];
__device__ uint32_t g_wo[(size_t)Cc * Cc];
__device__ uint32_t g_w1[(size_t)Cc * FFd];
__device__ uint32_t g_w2[(size_t)FFd * Cc];

__device__ __forceinline__ uint32_t f2tf32(float f) {
    uint32_t u;
    asm("cvt.rna.tf32.f32 %0, %1;" : "=r"(u) : "f"(f));
    return u;
}

// ---------------------------------------------------------------------------
// Weight convert: fp32 -> tf32 bits, vectorized. n % 1024 == 0.
// ---------------------------------------------------------------------------
__global__ __launch_bounds__(256) void cvt_kernel(
    const float* __restrict__ in, uint32_t* __restrict__ out, int n4)
{
    int i = blockIdx.x * 256 + threadIdx.x;
    if (i >= n4) return;
    float4 v = ((const float4*)in)[i];
    uint4 o;
    o.x = f2tf32(v.x); o.y = f2tf32(v.y); o.z = f2tf32(v.z); o.w = f2tf32(v.w);
    ((uint4*)out)[i] = o;
}

// ---------------------------------------------------------------------------
// LayerNorm: one block (256 threads) per row of 768; writes tf32 bits.
// ---------------------------------------------------------------------------
__device__ __forceinline__ float block_sum(float v, float* red) {
    #pragma unroll
    for (int o = 16; o > 0; o >>= 1) v += __shfl_xor_sync(0xffffffffu, v, o);
    int w = threadIdx.x >> 5;
    if ((threadIdx.x & 31) == 0) red[w] = v;
    __syncthreads();
    if (threadIdx.x == 0) {
        float t = 0.f;
        #pragma unroll
        for (int i = 0; i < 8; i++) t += red[i];
        red[0] = t;
    }
    __syncthreads();
    float r = red[0];
    __syncthreads();
    return r;
}

__global__ __launch_bounds__(256) void ln_kernel(
    const float* __restrict__ X, const float* __restrict__ g,
    const float* __restrict__ be, uint32_t* __restrict__ Y)
{
    __shared__ float red[8];
    int row = blockIdx.x, tid = threadIdx.x;
    const float* x = X + (size_t)row * Cc;
    float v0 = x[tid], v1 = x[tid + 256], v2 = x[tid + 512];
    float s  = block_sum(v0 + v1 + v2, red);
    float mu = s * (1.0f / Cc);
    float d0 = v0 - mu, d1 = v1 - mu, d2 = v2 - mu;
    float sq = block_sum(d0 * d0 + d1 * d1 + d2 * d2, red);
    float inv = rsqrtf(sq * (1.0f / Cc) + 1e-5f);
    uint32_t* y = Y + (size_t)row * Cc;
    y[tid]       = f2tf32(d0 * inv * g[tid]       + be[tid]);
    y[tid + 256] = f2tf32(d1 * inv * g[tid + 256] + be[tid + 256]);
    y[tid + 512] = f2tf32(d2 * inv * g[tid + 512] + be[tid + 512]);
}

// ---------------------------------------------------------------------------
// TF32 tensor-core GEMM: C[M,N] = A[M,K] @ B[K,N], A/B are tf32 bit patterns.
// 128x128x16 CTA tile, 8 warps (2x4), each warp 64x32 via m16n8k8 mma.
// 4-stage cp.async pipeline.
// EP: 0 = plain, 1 = resid + bias, 2 = gelu(acc + bias)
// OTF: 0 = fp32 out, 1 = tf32(u32) out
// ---------------------------------------------------------------------------
constexpr int GBK      = 16;
constexpr int GSTAGES  = 4;
constexpr int A_STRIDE = 20;    // u32 per A row (16 data + 4 pad), 80B (16B-mult)
constexpr int B_STRIDE = 132;   // u32 per B row (128 data + 4 pad), 528B
constexpr int A_STAGE  = 128 * A_STRIDE;          // 2560 u32
constexpr int B_STAGE  = GBK * B_STRIDE;          // 2112 u32
constexpr int STAGE_U32 = A_STAGE + B_STAGE;      // 4672 u32
constexpr int GEMM_SMEM = GSTAGES * STAGE_U32 * 4; // 74752 B

__device__ __forceinline__ void cpa16(uint32_t* s, const uint32_t* g) {
    uint32_t sa = (uint32_t)__cvta_generic_to_shared(s);
    asm volatile("cp.async.cg.shared.global [%0], [%1], 16;\n"
                 :: "r"(sa), "l"(g));
}

__device__ __forceinline__ void mma_tf32(
    float c[4], uint32_t a0, uint32_t a1, uint32_t a2, uint32_t a3,
    uint32_t b0, uint32_t b1)
{
    asm volatile(
        "mma.sync.aligned.m16n8k8.row.col.f32.tf32.tf32.f32 "
        "{%0,%1,%2,%3}, {%4,%5,%6,%7}, {%8,%9}, {%0,%1,%2,%3};"
        : "+f"(c[0]), "+f"(c[1]), "+f"(c[2]), "+f"(c[3])
        : "r"(a0), "r"(a1), "r"(a2), "r"(a3), "r"(b0), "r"(b1));
}

template<int EP, int OTF>
__global__ __launch_bounds__(256) void gemm_tc(
    const uint32_t* __restrict__ A, const uint32_t* __restrict__ Bm,
    const float* __restrict__ bias, const float* __restrict__ resid,
    void* __restrict__ Cout, int M, int N, int K)
{
    extern __shared__ uint32_t sm[];

    int tid  = threadIdx.x;
    int bm   = blockIdx.y * 128;
    int bn   = blockIdx.x * 128;
    int warp = tid >> 5;
    int lane = tid & 31;
    int wm   = warp >> 2;          // 0..1  (64 rows each)
    int wn   = warp & 3;           // 0..3  (32 cols each)
    int q    = lane & 3;           // 0..3
    int g    = lane >> 2;          // 0..7

    const uint32_t* Ag = A  + (size_t)bm * K;
    const uint32_t* Bg = Bm + bn;

    float acc[4][4][4];
    #pragma unroll
    for (int mt = 0; mt < 4; mt++)
        #pragma unroll
        for (int nt = 0; nt < 4; nt++)
            #pragma unroll
            for (int r = 0; r < 4; r++) acc[mt][nt][r] = 0.f;

    const int KT = K / GBK;

    auto prefetch = [&](int stage, int k0) {
        uint32_t* sA = sm + stage * STAGE_U32;
        uint32_t* sB = sA + A_STAGE;
        #pragma unroll
        for (int i = 0; i < 2; i++) {
            int id = tid + i * 256;          // 0..511
            int r  = id >> 2;                // 0..127
            int c  = (id & 3) << 2;          // 0,4,8,12
            cpa16(&sA[r * A_STRIDE + c], Ag + (size_t)r * K + k0 + c);
        }
        #pragma unroll
        for (int i = 0; i < 2; i++) {
            int id = tid + i * 256;          // 0..511
            int r  = id >> 5;                // 0..15
            int c  = (id & 31) << 2;         // 0..124
            cpa16(&sB[r * B_STRIDE + c], Bg + (size_t)(k0 + r) * N + c);
        }
    };

    // prologue: stages 0..2
    #pragma unroll
    for (int s = 0; s < GSTAGES - 1; s++) {
        prefetch(s, s * GBK);
        asm volatile("cp.async.commit_group;\n");
    }

    for (int kt = 0; kt < KT; kt++) {
        int pf = kt + GSTAGES - 1;
        if (pf < KT) prefetch(pf & 3, pf * GBK);
        asm volatile("cp.async.commit_group;\n");
        asm volatile("cp.async.wait_group %0;\n" :: "n"(GSTAGES - 1));
        __syncthreads();

        const uint32_t* sA = sm + (kt & 3) * STAGE_U32;
        const uint32_t* sB = sA + A_STAGE;

        #pragma unroll
        for (int ks = 0; ks < 2; ks++) {
            int kk = ks * 8 + q;
            uint32_t a[4][4];
            #pragma unroll
            for (int mt = 0; mt < 4; mt++) {
                const uint32_t* p = sA + (wm * 64 + mt * 16 + g) * A_STRIDE + kk;
                a[mt][0] = p[0];
                a[mt][1] = p[8 * A_STRIDE];
                a[mt][2] = p[4];
                a[mt][3] = p[8 * A_STRIDE + 4];
            }
            uint32_t b[4][2];
            #pragma unroll
            for (int nt = 0; nt < 4; nt++) {
                const uint32_t* p = sB + kk * B_STRIDE + wn * 32 + nt * 8 + g;
                b[nt][0] = p[0];
                b[nt][1] = p[4 * B_STRIDE];
            }
            #pragma unroll
            for (int mt = 0; mt < 4; mt++)
                #pragma unroll
                for (int nt = 0; nt < 4; nt++)
                    mma_tf32(acc[mt][nt], a[mt][0], a[mt][1], a[mt][2], a[mt][3],
                             b[nt][0], b[nt][1]);
        }
        __syncthreads();
    }

    // ---------------- epilogue ----------------
    #pragma unroll
    for (int nt = 0; nt < 4; nt++) {
        int c0 = bn + wn * 32 + nt * 8 + q * 2;
        float bb0 = 0.f, bb1 = 0.f;
        if (EP != 0) { bb0 = bias[c0]; bb1 = bias[c0 + 1]; }
        #pragma unroll
        for (int mt = 0; mt < 4; mt++) {
            #pragma unroll
            for (int half = 0; half < 2; half++) {
                int row = bm + wm * 64 + mt * 16 + g + half * 8;
                float v0 = acc[mt][nt][half * 2 + 0];
                float v1 = acc[mt][nt][half * 2 + 1];
                if (EP == 1) {
                    v0 += bb0; v1 += bb1;
                    float2 rr = *(const float2*)(resid + (size_t)row * N + c0);
                    v0 += rr.x; v1 += rr.y;
                }
                if (EP == 2) {
                    v0 += bb0; v1 += bb1;
                    v0 = 0.5f * v0 * (1.0f + erff(v0 * 0.70710678118654752f));
                    v1 = 0.5f * v1 * (1.0f + erff(v1 * 0.70710678118654752f));
                }
                if (OTF) {
                    uint2 ov; ov.x = f2tf32(v0); ov.y = f2tf32(v1);
                    *(uint2*)((uint32_t*)Cout + (size_t)row * N + c0) = ov;
                } else {
                    float2 ov; ov.x = v0; ov.y = v1;
                    *(float2*)((float*)Cout + (size_t)row * N + c0) = ov;
                }
            }
        }
    }
}

// ---------------------------------------------------------------------------
// Causal flash attention, fp32 compute; writes tf32-bit output (feeds GEMM).
// One CTA = 64 query rows of one (b,h). 256 threads, 4x4 register tiles.
// ---------------------------------------------------------------------------
constexpr int ATTN_SMEM_FLOATS = 64 * 65 + 64 * 64 + 64 * 64 + 64 * 65;
constexpr int ATTN_SMEM_BYTES  = ATTN_SMEM_FLOATS * 4;   // 66048

__global__ __launch_bounds__(256) void attn_kernel(
    const float* __restrict__ Q, const float* __restrict__ K,
    const float* __restrict__ V, uint32_t* __restrict__ O)
{
    extern __shared__ float smf[];
    float* sQ  = smf;                   // [64][65]
    float* sKt = sQ  + 64 * 65;         // [64(d)][64(j)]
    float* sV  = sKt + 64 * 64;         // [64(j)][64(d)]
    float* sP  = sV  + 64 * 64;         // [64][65]

    int tid = threadIdx.x;
    int ib  = blockIdx.x;
    int bh  = blockIdx.y;
    int b   = bh / NHh, h = bh % NHh;
    const size_t base = (size_t)b * Tt * Cc + (size_t)h * HSz;

    int tc = tid & 15, tr = tid >> 4;

    #pragma unroll
    for (int i = 0; i < 16; i++) {
        int idx = tid + i * 256;
        int r = idx >> 6, d = idx & 63;
        sQ[r * 65 + d] = Q[base + (size_t)(ib * 64 + r) * Cc + d];
    }

    float m[4], l[4], o[4][4];
    #pragma unroll
    for (int rr = 0; rr < 4; rr++) {
        m[rr] = -INFINITY; l[rr] = 0.f;
        #pragma unroll
        for (int cc = 0; cc < 4; cc++) o[rr][cc] = 0.f;
    }
    const float scale = 0.03608439182435161f;   // 768^-0.5 (C, not hs)

    for (int jb = 0; jb <= ib; jb++) {
        __syncthreads();
        #pragma unroll
        for (int i = 0; i < 16; i++) {
            int idx = tid + i * 256;
            int r = idx >> 6, d = idx & 63;
            float kv = K[base + (size_t)(jb * 64 + r) * Cc + d];
            float vv = V[base + (size_t)(jb * 64 + r) * Cc + d];
            sKt[d * 64 + r] = kv;
            sV [r * 64 + d] = vv;
        }
        __syncthreads();

        float s[4][4];
        #pragma unroll
        for (int rr = 0; rr < 4; rr++)
            #pragma unroll
            for (int cc = 0; cc < 4; cc++) s[rr][cc] = 0.f;

        #pragma unroll 4
        for (int d = 0; d < 64; d++) {
            float a0 = sQ[(tr * 4 + 0) * 65 + d];
            float a1 = sQ[(tr * 4 + 1) * 65 + d];
            float a2 = sQ[(tr * 4 + 2) * 65 + d];
            float a3 = sQ[(tr * 4 + 3) * 65 + d];
            float4 bbv = *(const float4*)(&sKt[d * 64 + tc * 4]);
            s[0][0] = fmaf(a0, bbv.x, s[0][0]); s[0][1] = fmaf(a0, bbv.y, s[0][1]);
            s[0][2] = fmaf(a0, bbv.z, s[0][2]); s[0][3] = fmaf(a0, bbv.w, s[0][3]);
            s[1][0] = fmaf(a1, bbv.x, s[1][0]); s[1][1] = fmaf(a1, bbv.y, s[1][1]);
            s[1][2] = fmaf(a1, bbv.z, s[1][2]); s[1][3] = fmaf(a1, bbv.w, s[1][3]);
            s[2][0] = fmaf(a2, bbv.x, s[2][0]); s[2][1] = fmaf(a2, bbv.y, s[2][1]);
            s[2][2] = fmaf(a2, bbv.z, s[2][2]); s[2][3] = fmaf(a2, bbv.w, s[2][3]);
            s[3][0] = fmaf(a3, bbv.x, s[3][0]); s[3][1] = fmaf(a3, bbv.y, s[3][1]);
            s[3][2] = fmaf(a3, bbv.z, s[3][2]); s[3][3] = fmaf(a3, bbv.w, s[3][3]);
        }

        int irow0 = ib * 64 + tr * 4;
        int jcol0 = jb * 64 + tc * 4;
        #pragma unroll
        for (int rr = 0; rr < 4; rr++)
            #pragma unroll
            for (int cc = 0; cc < 4; cc++) {
                float v = s[rr][cc] * scale;
                s[rr][cc] = (jcol0 + cc > irow0 + rr) ? -INFINITY : v;
            }

        #pragma unroll
        for (int rr = 0; rr < 4; rr++) {
            float bmax = fmaxf(fmaxf(s[rr][0], s[rr][1]), fmaxf(s[rr][2], s[rr][3]));
            #pragma unroll
            for (int off = 1; off < 16; off <<= 1)
                bmax = fmaxf(bmax, __shfl_xor_sync(0xffffffffu, bmax, off));
            float mn = fmaxf(m[rr], bmax);
            float sum = 0.f;
            #pragma unroll
            for (int cc = 0; cc < 4; cc++) {
                float p = __expf(s[rr][cc] - mn);
                s[rr][cc] = p;
                sum += p;
            }
            #pragma unroll
            for (int off = 1; off < 16; off <<= 1)
                sum += __shfl_xor_sync(0xffffffffu, sum, off);
            float alpha = __expf(m[rr] - mn);
            l[rr] = l[rr] * alpha + sum;
            m[rr] = mn;
            #pragma unroll
            for (int cc = 0; cc < 4; cc++) o[rr][cc] *= alpha;
            #pragma unroll
            for (int cc = 0; cc < 4; cc++)
                sP[(tr * 4 + rr) * 65 + tc * 4 + cc] = s[rr][cc];
        }
        __syncthreads();

        #pragma unroll 4
        for (int j = 0; j < 64; j++) {
            float4 vv = *(const float4*)(&sV[j * 64 + tc * 4]);
            float p0 = sP[(tr * 4 + 0) * 65 + j];
            float p1 = sP[(tr * 4 + 1) * 65 + j];
            float p2 = sP[(tr * 4 + 2) * 65 + j];
            float p3 = sP[(tr * 4 + 3) * 65 + j];
            o[0][0] = fmaf(p0, vv.x, o[0][0]); o[0][1] = fmaf(p0, vv.y, o[0][1]);
            o[0][2] = fmaf(p0, vv.z, o[0][2]); o[0][3] = fmaf(p0, vv.w, o[0][3]);
            o[1][0] = fmaf(p1, vv.x, o[1][0]); o[1][1] = fmaf(p1, vv.y, o[1][1]);
            o[1][2] = fmaf(p1, vv.z, o[1][2]); o[1][3] = fmaf(p1, vv.w, o[1][3]);
            o[2][0] = fmaf(p2, vv.x, o[2][0]); o[2][1] = fmaf(p2, vv.y, o[2][1]);
            o[2][2] = fmaf(p2, vv.z, o[2][2]); o[2][3] = fmaf(p2, vv.w, o[2][3]);
            o[3][0] = fmaf(p3, vv.x, o[3][0]); o[3][1] = fmaf(p3, vv.y, o[3][1]);
            o[3][2] = fmaf(p3, vv.z, o[3][2]); o[3][3] = fmaf(p3, vv.w, o[3][3]);
        }
    }

    #pragma unroll
    for (int rr = 0; rr < 4; rr++) {
        float inv = 1.0f / l[rr];
        size_t orow = base + (size_t)(ib * 64 + tr * 4 + rr) * Cc + tc * 4;
        uint4 ov;
        ov.x = f2tf32(o[rr][0] * inv); ov.y = f2tf32(o[rr][1] * inv);
        ov.z = f2tf32(o[rr][2] * inv); ov.w = f2tf32(o[rr][3] * inv);
        *(uint4*)(&O[orow]) = ov;
    }
}

// ---------------------------------------------------------------------------
// Launch
// ---------------------------------------------------------------------------
extern "C" void kernel_launch(void* const* d_in, const int* in_sizes, int n_in,
                              void* d_out, int out_size)
{
    const float* x   = (const float*)d_in[0];
    const float* Wq  = (const float*)d_in[1];
    const float* Wk  = (const float*)d_in[2];
    const float* Wv  = (const float*)d_in[3];
    const float* Wo  = (const float*)d_in[4];
    const float* bo  = (const float*)d_in[5];
    const float* W1  = (const float*)d_in[6];
    const float* b1  = (const float*)d_in[7];
    const float* W2  = (const float*)d_in[8];
    const float* b2  = (const float*)d_in[9];
    const float* g1  = (const float*)d_in[10];
    const float* be1 = (const float*)d_in[11];
    const float* g2  = (const float*)d_in[12];
    const float* be2 = (const float*)d_in[13];
    float* out = (float*)d_out;

    uint32_t *h, *o, *h2, *ff, *wq, *wk, *wv, *wo, *w1, *w2;
    float *q, *k, *v, *x2;
    cudaGetSymbolAddress((void**)&h,  g_h);
    cudaGetSymbolAddress((void**)&q,  g_q);
    cudaGetSymbolAddress((void**)&k,  g_k);
    cudaGetSymbolAddress((void**)&v,  g_v);
    cudaGetSymbolAddress((void**)&o,  g_o);
    cudaGetSymbolAddress((void**)&x2, g_x2);
    cudaGetSymbolAddress((void**)&h2, g_h2);
    cudaGetSymbolAddress((void**)&ff, g_ff);
    cudaGetSymbolAddress((void**)&wq, g_wq);
    cudaGetSymbolAddress((void**)&wk, g_wk);
    cudaGetSymbolAddress((void**)&wv, g_wv);
    cudaGetSymbolAddress((void**)&wo, g_wo);
    cudaGetSymbolAddress((void**)&w1, g_w1);
    cudaGetSymbolAddress((void**)&w2, g_w2);

    cudaFuncSetAttribute(attn_kernel,
        cudaFuncAttributeMaxDynamicSharedMemorySize, ATTN_SMEM_BYTES);
    cudaFuncSetAttribute(gemm_tc<0,0>,
        cudaFuncAttributeMaxDynamicSharedMemorySize, GEMM_SMEM);
    cudaFuncSetAttribute(gemm_tc<1,0>,
        cudaFuncAttributeMaxDynamicSharedMemorySize, GEMM_SMEM);
    cudaFuncSetAttribute(gemm_tc<2,1>,
        cudaFuncAttributeMaxDynamicSharedMemorySize, GEMM_SMEM);

    dim3 blk(256);
    dim3 g768(Cc / 128, MR / 128);    // (6, 64)
    dim3 g3072(FFd / 128, MR / 128);  // (24, 64)

    // one-shot (per call) weight conversion fp32 -> tf32
    int nCC = Cc * Cc / 4, nCF = Cc * FFd / 4;
    cvt_kernel<<<nCC / 256, blk>>>(Wq, wq, nCC);
    cvt_kernel<<<nCC / 256, blk>>>(Wk, wk, nCC);
    cvt_kernel<<<nCC / 256, blk>>>(Wv, wv, nCC);
    cvt_kernel<<<nCC / 256, blk>>>(Wo, wo, nCC);
    cvt_kernel<<<nCF / 256, blk>>>(W1, w1, nCF);
    cvt_kernel<<<nCF / 256, blk>>>(W2, w2, nCF);

    // h = LN(x) (tf32)
    ln_kernel<<<MR, blk>>>(x, g1, be1, h);
    // q/k/v = h @ W{q,k,v}  (fp32 out for attention)
    gemm_tc<0,0><<<g768, blk, GEMM_SMEM>>>(h, wq, nullptr, nullptr, q, MR, Cc, Cc);
    gemm_tc<0,0><<<g768, blk, GEMM_SMEM>>>(h, wk, nullptr, nullptr, k, MR, Cc, Cc);
    gemm_tc<0,0><<<g768, blk, GEMM_SMEM>>>(h, wv, nullptr, nullptr, v, MR, Cc, Cc);
    // causal attention (tf32 out)
    attn_kernel<<<dim3(Tt / 64, Bb * NHh), blk, ATTN_SMEM_BYTES>>>(q, k, v, o);
    // x2 = x + o @ Wo + bo
    gemm_tc<1,0><<<g768, blk, GEMM_SMEM>>>(o, wo, bo, x, x2, MR, Cc, Cc);
    // h2 = LN(x2) (tf32)
    ln_kernel<<<MR, blk>>>(x2, g2, be2, h2);
    // ff = gelu(h2 @ W1 + b1) (tf32)
    gemm_tc<2,1><<<g3072, blk, GEMM_SMEM>>>(h2, w1, b1, nullptr, ff, MR, FFd, Cc);
    // out = x2 + ff @ W2 + b2
    gemm_tc<1,0><<<g768, blk, GEMM_SMEM>>>(ff, w2, b2, x2, out, MR, Cc, FFd);
}

// round 4
// speedup vs baseline: 3.0713x; 1.3289x over previous
#include <cuda_runtime.h>
#include <math.h>
#include <stdint.h>

// ---------------------------------------------------------------------------
// Problem constants
// ---------------------------------------------------------------------------
constexpr int Bb   = 8;
constexpr int Tt   = 1024;
constexpr int Cc   = 768;
constexpr int NHh  = 12;
constexpr int HSz  = 64;
constexpr int MR   = Bb * Tt;      // 8192 rows
constexpr int FFd  = 4 * Cc;       // 3072
constexpr int QKVN = 3 * Cc;       // 2304

// ---------------------------------------------------------------------------
// Scratch (device globals; no cudaMalloc allowed)
// tf32 operands stored as uint32_t bit patterns.
// ---------------------------------------------------------------------------
__device__ uint32_t g_h   [(size_t)MR * Cc];     // LN1 out (tf32)
__device__ uint32_t g_qkv [(size_t)MR * QKVN];   // fused qkv out (tf32)
__device__ uint32_t g_o   [(size_t)MR * Cc];     // attn out (tf32)
__device__ float    g_x2  [(size_t)MR * Cc];
__device__ uint32_t g_h2  [(size_t)MR * Cc];     // LN2 out (tf32)
__device__ uint32_t g_ff  [(size_t)MR * FFd];    // gelu out (tf32)
__device__ uint32_t g_wqkv[(size_t)Cc * QKVN];   // packed Wq|Wk|Wv (tf32)
__device__ uint32_t g_wo  [(size_t)Cc * Cc];
__device__ uint32_t g_w1  [(size_t)Cc * FFd];
__device__ uint32_t g_w2  [(size_t)FFd * Cc];

__device__ __forceinline__ uint32_t f2tf32(float f) {
    uint32_t u;
    asm("cvt.rna.tf32.f32 %0, %1;" : "=r"(u) : "f"(f));
    return u;
}

// ---------------------------------------------------------------------------
// Weight converts
// ---------------------------------------------------------------------------
__global__ __launch_bounds__(256) void cvt_kernel(
    const float* __restrict__ in, uint32_t* __restrict__ out, int n4)
{
    int i = blockIdx.x * 256 + threadIdx.x;
    if (i >= n4) return;
    float4 v = ((const float4*)in)[i];
    uint4 o;
    o.x = f2tf32(v.x); o.y = f2tf32(v.y); o.z = f2tf32(v.z); o.w = f2tf32(v.w);
    ((uint4*)out)[i] = o;
}

// pack a [768,768] fp32 weight into g_wqkv[:, off:off+768] as tf32
__global__ __launch_bounds__(256) void cvt_pack_kernel(
    const float* __restrict__ in, uint32_t* __restrict__ out, int off)
{
    int i = blockIdx.x * 256 + threadIdx.x;      // float4 index, 147456 total
    int r  = i / (Cc / 4);
    int c4 = (i % (Cc / 4)) * 4;
    float4 v = ((const float4*)in)[i];
    uint4 o;
    o.x = f2tf32(v.x); o.y = f2tf32(v.y); o.z = f2tf32(v.z); o.w = f2tf32(v.w);
    *(uint4*)(out + (size_t)r * QKVN + off + c4) = o;
}

// ---------------------------------------------------------------------------
// LayerNorm: one block (256 threads) per row of 768; writes tf32 bits.
// ---------------------------------------------------------------------------
__device__ __forceinline__ float block_sum(float v, float* red) {
    #pragma unroll
    for (int o = 16; o > 0; o >>= 1) v += __shfl_xor_sync(0xffffffffu, v, o);
    int w = threadIdx.x >> 5;
    if ((threadIdx.x & 31) == 0) red[w] = v;
    __syncthreads();
    if (threadIdx.x == 0) {
        float t = 0.f;
        #pragma unroll
        for (int i = 0; i < 8; i++) t += red[i];
        red[0] = t;
    }
    __syncthreads();
    float r = red[0];
    __syncthreads();
    return r;
}

__global__ __launch_bounds__(256) void ln_kernel(
    const float* __restrict__ X, const float* __restrict__ g,
    const float* __restrict__ be, uint32_t* __restrict__ Y)
{
    __shared__ float red[8];
    int row = blockIdx.x, tid = threadIdx.x;
    const float* x = X + (size_t)row * Cc;
    float v0 = x[tid], v1 = x[tid + 256], v2 = x[tid + 512];
    float s  = block_sum(v0 + v1 + v2, red);
    float mu = s * (1.0f / Cc);
    float d0 = v0 - mu, d1 = v1 - mu, d2 = v2 - mu;
    float sq = block_sum(d0 * d0 + d1 * d1 + d2 * d2, red);
    float inv = rsqrtf(sq * (1.0f / Cc) + 1e-5f);
    uint32_t* y = Y + (size_t)row * Cc;
    y[tid]       = f2tf32(d0 * inv * g[tid]       + be[tid]);
    y[tid + 256] = f2tf32(d1 * inv * g[tid + 256] + be[tid + 256]);
    y[tid + 512] = f2tf32(d2 * inv * g[tid + 512] + be[tid + 512]);
}

// ---------------------------------------------------------------------------
// TF32 tensor-core GEMM (same as R3, validated).
// EP: 0 = plain, 1 = resid + bias, 2 = gelu(acc + bias)
// OTF: 0 = fp32 out, 1 = tf32(u32) out
// ---------------------------------------------------------------------------
constexpr int GBK      = 16;
constexpr int GSTAGES  = 4;
constexpr int A_STRIDE = 20;
constexpr int B_STRIDE = 132;
constexpr int A_STAGE  = 128 * A_STRIDE;
constexpr int B_STAGE  = GBK * B_STRIDE;
constexpr int STAGE_U32 = A_STAGE + B_STAGE;
constexpr int GEMM_SMEM = GSTAGES * STAGE_U32 * 4; // 74752 B

__device__ __forceinline__ void cpa16(uint32_t* s, const uint32_t* g) {
    uint32_t sa = (uint32_t)__cvta_generic_to_shared(s);
    asm volatile("cp.async.cg.shared.global [%0], [%1], 16;\n"
                 :: "r"(sa), "l"(g));
}

__device__ __forceinline__ void mma_tf32(
    float c[4], uint32_t a0, uint32_t a1, uint32_t a2, uint32_t a3,
    uint32_t b0, uint32_t b1)
{
    asm volatile(
        "mma.sync.aligned.m16n8k8.row.col.f32.tf32.tf32.f32 "
        "{%0,%1,%2,%3}, {%4,%5,%6,%7}, {%8,%9}, {%0,%1,%2,%3};"
        : "+f"(c[0]), "+f"(c[1]), "+f"(c[2]), "+f"(c[3])
        : "r"(a0), "r"(a1), "r"(a2), "r"(a3), "r"(b0), "r"(b1));
}

template<int EP, int OTF>
__global__ __launch_bounds__(256) void gemm_tc(
    const uint32_t* __restrict__ A, const uint32_t* __restrict__ Bm,
    const float* __restrict__ bias, const float* __restrict__ resid,
    void* __restrict__ Cout, int M, int N, int K)
{
    extern __shared__ uint32_t sm[];

    int tid  = threadIdx.x;
    int bm   = blockIdx.y * 128;
    int bn   = blockIdx.x * 128;
    int warp = tid >> 5;
    int lane = tid & 31;
    int wm   = warp >> 2;
    int wn   = warp & 3;
    int q    = lane & 3;
    int g    = lane >> 2;

    const uint32_t* Ag = A  + (size_t)bm * K;
    const uint32_t* Bg = Bm + bn;

    float acc[4][4][4];
    #pragma unroll
    for (int mt = 0; mt < 4; mt++)
        #pragma unroll
        for (int nt = 0; nt < 4; nt++)
            #pragma unroll
            for (int r = 0; r < 4; r++) acc[mt][nt][r] = 0.f;

    const int KT = K / GBK;

    auto prefetch = [&](int stage, int k0) {
        uint32_t* sA = sm + stage * STAGE_U32;
        uint32_t* sB = sA + A_STAGE;
        #pragma unroll
        for (int i = 0; i < 2; i++) {
            int id = tid + i * 256;
            int r  = id >> 2;
            int c  = (id & 3) << 2;
            cpa16(&sA[r * A_STRIDE + c], Ag + (size_t)r * K + k0 + c);
        }
        #pragma unroll
        for (int i = 0; i < 2; i++) {
            int id = tid + i * 256;
            int r  = id >> 5;
            int c  = (id & 31) << 2;
            cpa16(&sB[r * B_STRIDE + c], Bg + (size_t)(k0 + r) * N + c);
        }
    };

    #pragma unroll
    for (int s = 0; s < GSTAGES - 1; s++) {
        prefetch(s, s * GBK);
        asm volatile("cp.async.commit_group;\n");
    }

    for (int kt = 0; kt < KT; kt++) {
        int pf = kt + GSTAGES - 1;
        if (pf < KT) prefetch(pf & 3, pf * GBK);
        asm volatile("cp.async.commit_group;\n");
        asm volatile("cp.async.wait_group %0;\n" :: "n"(GSTAGES - 1));
        __syncthreads();

        const uint32_t* sA = sm + (kt & 3) * STAGE_U32;
        const uint32_t* sB = sA + A_STAGE;

        #pragma unroll
        for (int ks = 0; ks < 2; ks++) {
            int kk = ks * 8 + q;
            uint32_t a[4][4];
            #pragma unroll
            for (int mt = 0; mt < 4; mt++) {
                const uint32_t* p = sA + (wm * 64 + mt * 16 + g) * A_STRIDE + kk;
                a[mt][0] = p[0];
                a[mt][1] = p[8 * A_STRIDE];
                a[mt][2] = p[4];
                a[mt][3] = p[8 * A_STRIDE + 4];
            }
            uint32_t b[4][2];
            #pragma unroll
            for (int nt = 0; nt < 4; nt++) {
                const uint32_t* p = sB + kk * B_STRIDE + wn * 32 + nt * 8 + g;
                b[nt][0] = p[0];
                b[nt][1] = p[4 * B_STRIDE];
            }
            #pragma unroll
            for (int mt = 0; mt < 4; mt++)
                #pragma unroll
                for (int nt = 0; nt < 4; nt++)
                    mma_tf32(acc[mt][nt], a[mt][0], a[mt][1], a[mt][2], a[mt][3],
                             b[nt][0], b[nt][1]);
        }
        __syncthreads();
    }

    #pragma unroll
    for (int nt = 0; nt < 4; nt++) {
        int c0 = bn + wn * 32 + nt * 8 + q * 2;
        float bb0 = 0.f, bb1 = 0.f;
        if (EP != 0) { bb0 = bias[c0]; bb1 = bias[c0 + 1]; }
        #pragma unroll
        for (int mt = 0; mt < 4; mt++) {
            #pragma unroll
            for (int half = 0; half < 2; half++) {
                int row = bm + wm * 64 + mt * 16 + g + half * 8;
                float v0 = acc[mt][nt][half * 2 + 0];
                float v1 = acc[mt][nt][half * 2 + 1];
                if (EP == 1) {
                    v0 += bb0; v1 += bb1;
                    float2 rr = *(const float2*)(resid + (size_t)row * N + c0);
                    v0 += rr.x; v1 += rr.y;
                }
                if (EP == 2) {
                    v0 += bb0; v1 += bb1;
                    v0 = 0.5f * v0 * (1.0f + erff(v0 * 0.70710678118654752f));
                    v1 = 0.5f * v1 * (1.0f + erff(v1 * 0.70710678118654752f));
                }
                if (OTF) {
                    uint2 ov; ov.x = f2tf32(v0); ov.y = f2tf32(v1);
                    *(uint2*)((uint32_t*)Cout + (size_t)row * N + c0) = ov;
                } else {
                    float2 ov; ov.x = v0; ov.y = v1;
                    *(float2*)((float*)Cout + (size_t)row * N + c0) = ov;
                }
            }
        }
    }
}

// ---------------------------------------------------------------------------
// Tensor-core causal flash attention (tf32 mma, fp32 softmax).
// One CTA = 64 query rows of one (b,h). 128 threads / 4 warps; warp w owns
// rows [w*16, w*16+16). S = Q K^T and O += P V via m16n8k8 tf32 mma.
// P is warp-local (sP aliases sQ region; only __syncwarp between P write/read).
// ---------------------------------------------------------------------------
constexpr int AQS = 68;   // sQ/sP row stride (u32): (g*68+q)%32 = 4g+q, conflict-free
constexpr int AKS = 72;   // sKt/sV row stride: (q*72+g)%32 = 8q+g, conflict-free
constexpr int ATTN_SMEM_U32 = 64 * AQS + 64 * AKS + 64 * AKS;  // 13568
constexpr int ATTN_SMEM_BYTES = ATTN_SMEM_U32 * 4;             // 54272

__global__ __launch_bounds__(128) void attn_kernel(
    const uint32_t* __restrict__ qkv, uint32_t* __restrict__ O)
{
    extern __shared__ uint32_t smu[];
    uint32_t* sQ  = smu;                 // [64][AQS]  (aliased as sP after Q frags)
    uint32_t* sKt = sQ  + 64 * AQS;      // [d:64][j:64] stride AKS
    uint32_t* sV  = sKt + 64 * AKS;      // [j:64][d:64] stride AKS

    int tid = threadIdx.x;
    int w   = tid >> 5;
    int lane = tid & 31;
    int q   = lane & 3;
    int g   = lane >> 2;
    int m0  = w * 16;

    int ib  = blockIdx.x;
    int bh  = blockIdx.y;
    int b   = bh / NHh, h = bh % NHh;
    int rowbase = b * Tt + ib * 64;
    int qo = h * HSz, ko = Cc + h * HSz, vo = 2 * Cc + h * HSz;

    const float NEG_INF = __int_as_float(0xff800000);

    // ---- load Q tile (64 x 64 u32) ----
    #pragma unroll
    for (int i = 0; i < 8; i++) {
        int u4 = tid + i * 128;          // 0..1023
        int r  = u4 >> 4;
        int c4 = (u4 & 15) << 2;
        uint4 v = *(const uint4*)(qkv + (size_t)(rowbase + r) * QKVN + qo + c4);
        *(uint4*)(sQ + r * AQS + c4) = v;
    }
    __syncthreads();

    // ---- hoist Q fragments to registers (warp-local rows) ----
    uint32_t aq[8][4];
    #pragma unroll
    for (int ks = 0; ks < 8; ks++) {
        const uint32_t* p = sQ + (m0 + g) * AQS + ks * 8 + q;
        aq[ks][0] = p[0];
        aq[ks][1] = p[8 * AQS];
        aq[ks][2] = p[4];
        aq[ks][3] = p[8 * AQS + 4];
    }
    // after this, sQ rows [m0, m0+16) are reused as this warp's sP.
    uint32_t* sP = sQ + m0 * AQS;

    float mA = NEG_INF, mB = NEG_INF, lA = 0.f, lB = 0.f;
    float o[8][4];
    #pragma unroll
    for (int nt = 0; nt < 8; nt++)
        #pragma unroll
        for (int r = 0; r < 4; r++) o[nt][r] = 0.f;

    const float scale = 0.03608439182435161f;   // 768^-0.5 (C, not hs)

    for (int jb = 0; jb <= ib; jb++) {
        if (jb) __syncthreads();     // protect sKt/sV reuse
        // ---- load K (transposed) and V tiles ----
        int krow = b * Tt + jb * 64;
        #pragma unroll
        for (int i = 0; i < 8; i++) {
            int u4 = tid + i * 128;
            int r  = u4 >> 4;
            int c4 = (u4 & 15) << 2;
            uint4 kv = *(const uint4*)(qkv + (size_t)(krow + r) * QKVN + ko + c4);
            sKt[(c4 + 0) * AKS + r] = kv.x;
            sKt[(c4 + 1) * AKS + r] = kv.y;
            sKt[(c4 + 2) * AKS + r] = kv.z;
            sKt[(c4 + 3) * AKS + r] = kv.w;
            uint4 vv = *(const uint4*)(qkv + (size_t)(krow + r) * QKVN + vo + c4);
            *(uint4*)(sV + r * AKS + c4) = vv;
        }
        __syncthreads();

        // ---- S = Q K^T ----
        float sacc[8][4];
        #pragma unroll
        for (int nt = 0; nt < 8; nt++)
            #pragma unroll
            for (int r = 0; r < 4; r++) sacc[nt][r] = 0.f;

        #pragma unroll
        for (int ks = 0; ks < 8; ks++) {
            int kk = ks * 8 + q;
            #pragma unroll
            for (int nt = 0; nt < 8; nt++) {
                uint32_t b0 = sKt[kk * AKS + nt * 8 + g];
                uint32_t b1 = sKt[(kk + 4) * AKS + nt * 8 + g];
                mma_tf32(sacc[nt], aq[ks][0], aq[ks][1], aq[ks][2], aq[ks][3], b0, b1);
            }
        }

        // ---- scale + causal mask ----
        bool diag = (jb == ib);
        #pragma unroll
        for (int nt = 0; nt < 8; nt++) {
            #pragma unroll
            for (int r = 0; r < 4; r++) {
                float v = sacc[nt][r] * scale;
                if (diag) {
                    int lrow = m0 + g + ((r >= 2) ? 8 : 0);
                    int lcol = nt * 8 + 2 * q + (r & 1);
                    if (lcol > lrow) v = NEG_INF;
                }
                sacc[nt][r] = v;
            }
        }

        // ---- online softmax: row A = g, row B = g+8 ----
        float bmaxA = NEG_INF, bmaxB = NEG_INF;
        #pragma unroll
        for (int nt = 0; nt < 8; nt++) {
            bmaxA = fmaxf(bmaxA, fmaxf(sacc[nt][0], sacc[nt][1]));
            bmaxB = fmaxf(bmaxB, fmaxf(sacc[nt][2], sacc[nt][3]));
        }
        #pragma unroll
        for (int off = 1; off < 4; off <<= 1) {
            bmaxA = fmaxf(bmaxA, __shfl_xor_sync(0xffffffffu, bmaxA, off));
            bmaxB = fmaxf(bmaxB, __shfl_xor_sync(0xffffffffu, bmaxB, off));
        }
        float mnA = fmaxf(mA, bmaxA), mnB = fmaxf(mB, bmaxB);
        float sumA = 0.f, sumB = 0.f;
        #pragma unroll
        for (int nt = 0; nt < 8; nt++) {
            float p0 = __expf(sacc[nt][0] - mnA);
            float p1 = __expf(sacc[nt][1] - mnA);
            float p2 = __expf(sacc[nt][2] - mnB);
            float p3 = __expf(sacc[nt][3] - mnB);
            sumA += p0 + p1; sumB += p2 + p3;
            sacc[nt][0] = p0; sacc[nt][1] = p1;
            sacc[nt][2] = p2; sacc[nt][3] = p3;
        }
        #pragma unroll
        for (int off = 1; off < 4; off <<= 1) {
            sumA += __shfl_xor_sync(0xffffffffu, sumA, off);
            sumB += __shfl_xor_sync(0xffffffffu, sumB, off);
        }
        float alphaA = __expf(mA - mnA), alphaB = __expf(mB - mnB);
        lA = lA * alphaA + sumA; lB = lB * alphaB + sumB;
        mA = mnA; mB = mnB;
        #pragma unroll
        for (int nt = 0; nt < 8; nt++) {
            o[nt][0] *= alphaA; o[nt][1] *= alphaA;
            o[nt][2] *= alphaB; o[nt][3] *= alphaB;
        }

        // ---- write P (tf32) to warp-local sP ----
        #pragma unroll
        for (int nt = 0; nt < 8; nt++) {
            uint2 pa; pa.x = f2tf32(sacc[nt][0]); pa.y = f2tf32(sacc[nt][1]);
            *(uint2*)(sP + g * AQS + nt * 8 + 2 * q) = pa;
            uint2 pb; pb.x = f2tf32(sacc[nt][2]); pb.y = f2tf32(sacc[nt][3]);
            *(uint2*)(sP + (g + 8) * AQS + nt * 8 + 2 * q) = pb;
        }
        __syncwarp();

        // ---- O += P V ----
        #pragma unroll
        for (int ks = 0; ks < 8; ks++) {
            int kk = ks * 8 + q;
            const uint32_t* pp = sP + g * AQS + kk;
            uint32_t a0 = pp[0];
            uint32_t a1 = pp[8 * AQS];
            uint32_t a2 = pp[4];
            uint32_t a3 = pp[8 * AQS + 4];
            #pragma unroll
            for (int nt = 0; nt < 8; nt++) {
                uint32_t b0 = sV[kk * AKS + nt * 8 + g];
                uint32_t b1 = sV[(kk + 4) * AKS + nt * 8 + g];
                mma_tf32(o[nt], a0, a1, a2, a3, b0, b1);
            }
        }
        __syncwarp();   // protect sP before next iteration rewrite
    }

    // ---- epilogue: normalize, convert, store ----
    float invA = 1.0f / lA, invB = 1.0f / lB;
    #pragma unroll
    for (int nt = 0; nt < 8; nt++) {
        int col = h * HSz + nt * 8 + 2 * q;
        int rA = rowbase + m0 + g;
        int rB = rA + 8;
        uint2 oa; oa.x = f2tf32(o[nt][0] * invA); oa.y = f2tf32(o[nt][1] * invA);
        *(uint2*)(O + (size_t)rA * Cc + col) = oa;
        uint2 ob; ob.x = f2tf32(o[nt][2] * invB); ob.y = f2tf32(o[nt][3] * invB);
        *(uint2*)(O + (size_t)rB * Cc + col) = ob;
    }
}

// ---------------------------------------------------------------------------
// Launch
// ---------------------------------------------------------------------------
extern "C" void kernel_launch(void* const* d_in, const int* in_sizes, int n_in,
                              void* d_out, int out_size)
{
    const float* x   = (const float*)d_in[0];
    const float* Wq  = (const float*)d_in[1];
    const float* Wk  = (const float*)d_in[2];
    const float* Wv  = (const float*)d_in[3];
    const float* Wo  = (const float*)d_in[4];
    const float* bo  = (const float*)d_in[5];
    const float* W1  = (const float*)d_in[6];
    const float* b1  = (const float*)d_in[7];
    const float* W2  = (const float*)d_in[8];
    const float* b2  = (const float*)d_in[9];
    const float* g1  = (const float*)d_in[10];
    const float* be1 = (const float*)d_in[11];
    const float* g2  = (const float*)d_in[12];
    const float* be2 = (const float*)d_in[13];
    float* out = (float*)d_out;

    uint32_t *h, *qkv, *o, *h2, *ff, *wqkv, *wo, *w1, *w2;
    float *x2;
    cudaGetSymbolAddress((void**)&h,    g_h);
    cudaGetSymbolAddress((void**)&qkv,  g_qkv);
    cudaGetSymbolAddress((void**)&o,    g_o);
    cudaGetSymbolAddress((void**)&x2,   g_x2);
    cudaGetSymbolAddress((void**)&h2,   g_h2);
    cudaGetSymbolAddress((void**)&ff,   g_ff);
    cudaGetSymbolAddress((void**)&wqkv, g_wqkv);
    cudaGetSymbolAddress((void**)&wo,   g_wo);
    cudaGetSymbolAddress((void**)&w1,   g_w1);
    cudaGetSymbolAddress((void**)&w2,   g_w2);

    cudaFuncSetAttribute(attn_kernel,
        cudaFuncAttributeMaxDynamicSharedMemorySize, ATTN_SMEM_BYTES);
    cudaFuncSetAttribute(gemm_tc<0,1>,
        cudaFuncAttributeMaxDynamicSharedMemorySize, GEMM_SMEM);
    cudaFuncSetAttribute(gemm_tc<1,0>,
        cudaFuncAttributeMaxDynamicSharedMemorySize, GEMM_SMEM);
    cudaFuncSetAttribute(gemm_tc<2,1>,
        cudaFuncAttributeMaxDynamicSharedMemorySize, GEMM_SMEM);

    dim3 blk(256);
    dim3 g768 (Cc   / 128, MR / 128);   // (6, 64)
    dim3 gqkv (QKVN / 128, MR / 128);   // (18, 64)
    dim3 g3072(FFd  / 128, MR / 128);   // (24, 64)

    // weight conversion fp32 -> tf32 (Wq/Wk/Wv packed into one buffer)
    int nCC = Cc * Cc / 4, nCF = Cc * FFd / 4;
    cvt_pack_kernel<<<nCC / 256, blk>>>(Wq, wqkv, 0);
    cvt_pack_kernel<<<nCC / 256, blk>>>(Wk, wqkv, Cc);
    cvt_pack_kernel<<<nCC / 256, blk>>>(Wv, wqkv, 2 * Cc);
    cvt_kernel<<<nCC / 256, blk>>>(Wo, wo, nCC);
    cvt_kernel<<<nCF / 256, blk>>>(W1, w1, nCF);
    cvt_kernel<<<nCF / 256, blk>>>(W2, w2, nCF);

    // h = LN(x) (tf32)
    ln_kernel<<<MR, blk>>>(x, g1, be1, h);
    // qkv = h @ [Wq|Wk|Wv]  (tf32 out)
    gemm_tc<0,1><<<gqkv, blk, GEMM_SMEM>>>(h, wqkv, nullptr, nullptr, qkv, MR, QKVN, Cc);
    // causal attention (tf32 out)
    attn_kernel<<<dim3(Tt / 64, Bb * NHh), dim3(128), ATTN_SMEM_BYTES>>>(qkv, o);
    // x2 = x + o @ Wo + bo
    gemm_tc<1,0><<<g768, blk, GEMM_SMEM>>>(o, wo, bo, x, x2, MR, Cc, Cc);
    // h2 = LN(x2) (tf32)
    ln_kernel<<<MR, blk>>>(x2, g2, be2, h2);
    // ff = gelu(h2 @ W1 + b1) (tf32)
    gemm_tc<2,1><<<g3072, blk, GEMM_SMEM>>>(h2, w1, b1, nullptr, ff, MR, FFd, Cc);
    // out = x2 + ff @ W2 + b2
    gemm_tc<1,0><<<g768, blk, GEMM_SMEM>>>(ff, w2, b2, x2, out, MR, Cc, FFd);
}

// round 15
// speedup vs baseline: 5.7274x; 1.8648x over previous
#include <cuda_runtime.h>
#include <math.h>
#include <stdint.h>

// ---------------------------------------------------------------------------
// Problem constants
// ---------------------------------------------------------------------------
constexpr int Bb   = 8;
constexpr int Tt   = 1024;
constexpr int Cc   = 768;
constexpr int NHh  = 12;
constexpr int HSz  = 64;
constexpr int MR   = Bb * Tt;      // 8192 rows
constexpr int FFd  = 4 * Cc;       // 3072
constexpr int QKVN = 3 * Cc;       // 2304

// u32 (half2) row strides
constexpr int CU   = Cc / 2;       // 384
constexpr int QKVU = QKVN / 2;     // 1152
constexpr int FFU  = FFd / 2;      // 1536

// ---------------------------------------------------------------------------
// Scratch (device globals). fp16 data stored as uint32_t = half2 (k-pairs).
// ---------------------------------------------------------------------------
__device__ uint32_t g_h   [(size_t)MR * CU];      // LN1 out
__device__ uint32_t g_qkv [(size_t)MR * QKVU];    // fused qkv out
__device__ uint32_t g_o   [(size_t)MR * CU];      // attn out
__device__ float    g_x2  [(size_t)MR * Cc];      // residual stream (fp32)
__device__ uint32_t g_h2  [(size_t)MR * CU];      // LN2 out
__device__ uint32_t g_ff  [(size_t)MR * FFU];     // gelu out
__device__ uint32_t g_wqkv[(size_t)CU * QKVN];    // packed Wq|Wk|Wv, k-pairs
__device__ uint32_t g_wo  [(size_t)CU * Cc];
__device__ uint32_t g_w1  [(size_t)CU * FFd];
__device__ uint32_t g_w2  [(size_t)FFU * Cc];

// pack two fp32 -> half2 u32 {lo, hi}
__device__ __forceinline__ uint32_t f2h2(float lo, float hi) {
    uint32_t d;
    asm("cvt.rn.f16x2.f32 %0, %1, %2;" : "=r"(d) : "f"(hi), "f"(lo));
    return d;
}

// ---------------------------------------------------------------------------
// Weight convert: fp32 [K][Nin] -> k-pair-packed half2 u32 [K/2][ldout] at off
// ---------------------------------------------------------------------------
__global__ __launch_bounds__(256) void cvt_pack_kernel(
    const float* __restrict__ in, uint32_t* __restrict__ out,
    int Nin, int ldout, int off, int total)
{
    int i = blockIdx.x * 256 + threadIdx.x;
    if (i >= total) return;
    int kk = i / Nin;
    int n  = i - kk * Nin;
    float a = in[(size_t)(2 * kk)     * Nin + n];
    float b = in[(size_t)(2 * kk + 1) * Nin + n];
    out[(size_t)kk * ldout + off + n] = f2h2(a, b);
}

// ---------------------------------------------------------------------------
// LayerNorm: one block (256 thr, 192 active) per row of 768; writes half2.
// ---------------------------------------------------------------------------
__device__ __forceinline__ float block_sum(float v, float* red) {
    #pragma unroll
    for (int o = 16; o > 0; o >>= 1) v += __shfl_xor_sync(0xffffffffu, v, o);
    int w = threadIdx.x >> 5;
    if ((threadIdx.x & 31) == 0) red[w] = v;
    __syncthreads();
    if (threadIdx.x == 0) {
        float t = 0.f;
        #pragma unroll
        for (int i = 0; i < 8; i++) t += red[i];
        red[0] = t;
    }
    __syncthreads();
    float r = red[0];
    __syncthreads();
    return r;
}

__global__ __launch_bounds__(256) void ln_kernel(
    const float* __restrict__ X, const float* __restrict__ g,
    const float* __restrict__ be, uint32_t* __restrict__ Y)
{
    __shared__ float red[8];
    int row = blockIdx.x, tid = threadIdx.x;
    bool act = tid < 192;
    float4 v = make_float4(0.f, 0.f, 0.f, 0.f);
    if (act) v = ((const float4*)(X + (size_t)row * Cc))[tid];
    float s  = block_sum(v.x + v.y + v.z + v.w, red);
    float mu = s * (1.0f / Cc);
    float d0 = v.x - mu, d1 = v.y - mu, d2 = v.z - mu, d3 = v.w - mu;
    float c = act ? (d0 * d0 + d1 * d1 + d2 * d2 + d3 * d3) : 0.f;
    float sq = block_sum(c, red);
    float inv = rsqrtf(sq * (1.0f / Cc) + 1e-5f);
    if (act) {
        float4 gg = ((const float4*)g)[tid];
        float4 bb = ((const float4*)be)[tid];
        float y0 = d0 * inv * gg.x + bb.x;
        float y1 = d1 * inv * gg.y + bb.y;
        float y2 = d2 * inv * gg.z + bb.z;
        float y3 = d3 * inv * gg.w + bb.w;
        uint2 o;
        o.x = f2h2(y0, y1); o.y = f2h2(y2, y3);
        *(uint2*)(Y + (size_t)row * CU + tid * 2) = o;
    }
}

// ---------------------------------------------------------------------------
// FP16 tensor-core GEMM: C[M,N] = A[M,K] @ B[K,N]; A/B half2-packed u32.
// KU = K/2 (u32 units). 128x128 CTA tile, k-tile = 16 u32 = 32 halves.
// 8 warps (2x4), warp tile 64x32 via m16n8k16. 4-stage cp.async.
// EP: 0 = plain, 1 = resid+bias (fp32 out), 2 = gelu(acc+bias)
// OH: 0 = fp32 out, 1 = half2 out
// ---------------------------------------------------------------------------
constexpr int GBK      = 16;     // u32 per k-tile (= 32 halves)
constexpr int GSTAGES  = 4;
constexpr int A_STRIDE = 20;
constexpr int B_STRIDE = 132;
constexpr int A_STAGE  = 128 * A_STRIDE;
constexpr int B_STAGE  = GBK * B_STRIDE;
constexpr int STAGE_U32 = A_STAGE + B_STAGE;
constexpr int GEMM_SMEM = GSTAGES * STAGE_U32 * 4; // 74752 B

__device__ __forceinline__ void cpa16(uint32_t* s, const uint32_t* g) {
    uint32_t sa = (uint32_t)__cvta_generic_to_shared(s);
    asm volatile("cp.async.cg.shared.global [%0], [%1], 16;\n"
                 :: "r"(sa), "l"(g));
}

__device__ __forceinline__ void mma_f16(
    float c[4], uint32_t a0, uint32_t a1, uint32_t a2, uint32_t a3,
    uint32_t b0, uint32_t b1)
{
    asm volatile(
        "mma.sync.aligned.m16n8k16.row.col.f32.f16.f16.f32 "
        "{%0,%1,%2,%3}, {%4,%5,%6,%7}, {%8,%9}, {%0,%1,%2,%3};"
        : "+f"(c[0]), "+f"(c[1]), "+f"(c[2]), "+f"(c[3])
        : "r"(a0), "r"(a1), "r"(a2), "r"(a3), "r"(b0), "r"(b1));
}

template<int EP, int OH>
__global__ __launch_bounds__(256) void gemm_tc(
    const uint32_t* __restrict__ A, const uint32_t* __restrict__ Bm,
    const float* __restrict__ bias, const float* __restrict__ resid,
    void* __restrict__ Cout, int M, int N, int KU)
{
    extern __shared__ uint32_t sm[];

    int tid  = threadIdx.x;
    int bm   = blockIdx.y * 128;
    int bn   = blockIdx.x * 128;
    int warp = tid >> 5;
    int lane = tid & 31;
    int wm   = warp >> 2;
    int wn   = warp & 3;
    int q    = lane & 3;
    int g    = lane >> 2;

    const uint32_t* Ag = A  + (size_t)bm * KU;
    const uint32_t* Bg = Bm + bn;

    float acc[4][4][4];
    #pragma unroll
    for (int mt = 0; mt < 4; mt++)
        #pragma unroll
        for (int nt = 0; nt < 4; nt++)
            #pragma unroll
            for (int r = 0; r < 4; r++) acc[mt][nt][r] = 0.f;

    const int KT = KU / GBK;

    auto prefetch = [&](int stage, int k0) {
        uint32_t* sA = sm + stage * STAGE_U32;
        uint32_t* sB = sA + A_STAGE;
        #pragma unroll
        for (int i = 0; i < 2; i++) {
            int id = tid + i * 256;
            int r  = id >> 2;
            int c  = (id & 3) << 2;
            cpa16(&sA[r * A_STRIDE + c], Ag + (size_t)r * KU + k0 + c);
        }
        #pragma unroll
        for (int i = 0; i < 2; i++) {
            int id = tid + i * 256;
            int r  = id >> 5;
            int c  = (id & 31) << 2;
            cpa16(&sB[r * B_STRIDE + c], Bg + (size_t)(k0 + r) * N + c);
        }
    };

    #pragma unroll
    for (int s = 0; s < GSTAGES - 1; s++) {
        prefetch(s, s * GBK);
        asm volatile("cp.async.commit_group;\n");
    }

    for (int kt = 0; kt < KT; kt++) {
        int pf = kt + GSTAGES - 1;
        if (pf < KT) prefetch(pf & 3, pf * GBK);
        asm volatile("cp.async.commit_group;\n");
        asm volatile("cp.async.wait_group %0;\n" :: "n"(GSTAGES - 1));
        __syncthreads();

        const uint32_t* sA = sm + (kt & 3) * STAGE_U32;
        const uint32_t* sB = sA + A_STAGE;

        #pragma unroll
        for (int ks = 0; ks < 2; ks++) {
            int kk = ks * 8 + q;
            uint32_t a[4][4];
            #pragma unroll
            for (int mt = 0; mt < 4; mt++) {
                const uint32_t* p = sA + (wm * 64 + mt * 16 + g) * A_STRIDE + kk;
                a[mt][0] = p[0];
                a[mt][1] = p[8 * A_STRIDE];
                a[mt][2] = p[4];
                a[mt][3] = p[8 * A_STRIDE + 4];
            }
            uint32_t b[4][2];
            #pragma unroll
            for (int nt = 0; nt < 4; nt++) {
                const uint32_t* p = sB + kk * B_STRIDE + wn * 32 + nt * 8 + g;
                b[nt][0] = p[0];
                b[nt][1] = p[4 * B_STRIDE];
            }
            #pragma unroll
            for (int mt = 0; mt < 4; mt++)
                #pragma unroll
                for (int nt = 0; nt < 4; nt++)
                    mma_f16(acc[mt][nt], a[mt][0], a[mt][1], a[mt][2], a[mt][3],
                            b[nt][0], b[nt][1]);
        }
        __syncthreads();
    }

    // ---------------- epilogue ----------------
    #pragma unroll
    for (int nt = 0; nt < 4; nt++) {
        int c0 = bn + wn * 32 + nt * 8 + q * 2;
        float bb0 = 0.f, bb1 = 0.f;
        if (EP != 0) { bb0 = bias[c0]; bb1 = bias[c0 + 1]; }
        #pragma unroll
        for (int mt = 0; mt < 4; mt++) {
            #pragma unroll
            for (int half = 0; half < 2; half++) {
                int row = bm + wm * 64 + mt * 16 + g + half * 8;
                float v0 = acc[mt][nt][half * 2 + 0];
                float v1 = acc[mt][nt][half * 2 + 1];
                if (EP == 1) {
                    v0 += bb0; v1 += bb1;
                    float2 rr = *(const float2*)(resid + (size_t)row * N + c0);
                    v0 += rr.x; v1 += rr.y;
                }
                if (EP == 2) {
                    v0 += bb0; v1 += bb1;
                    v0 = 0.5f * v0 * (1.0f + erff(v0 * 0.70710678118654752f));
                    v1 = 0.5f * v1 * (1.0f + erff(v1 * 0.70710678118654752f));
                }
                if (OH) {
                    ((uint32_t*)Cout)[(size_t)row * (N / 2) + c0 / 2] = f2h2(v0, v1);
                } else {
                    float2 ov; ov.x = v0; ov.y = v1;
                    *(float2*)((float*)Cout + (size_t)row * N + c0) = ov;
                }
            }
        }
    }
}

// ---------------------------------------------------------------------------
// FP16 tensor-core causal flash attention.
// One CTA = 64 query rows of one (b,h). 128 threads / 4 warps; warp w owns
// rows [w*16, w*16+16). S = QK^T and O += PV via m16n8k16.
// qkv: u32[MR][QKVU]. Output O: u32[MR][CU] (half2).
// ---------------------------------------------------------------------------
constexpr int AQS = 36;   // sQ stride (u32/dpair), banks (4g+q) distinct
constexpr int AKS = 72;   // sKt/sV stride, banks (8q+g) distinct
constexpr int APS = 36;   // sP stride
__global__ __launch_bounds__(128) void attn_kernel(
    const uint32_t* __restrict__ qkv, uint32_t* __restrict__ O)
{
    __shared__ uint32_t sQ [64 * AQS];        // [row][dpair]
    __shared__ uint32_t sKt[32 * AKS];        // [dpair][j]
    __shared__ uint32_t sV [32 * AKS];        // [jpair][d(half col)]
    __shared__ uint32_t sPa[4 * 16 * APS];    // per-warp P [row][jpair]

    int tid = threadIdx.x;
    int w    = tid >> 5;
    int lane = tid & 31;
    int q    = lane & 3;
    int g    = lane >> 2;
    int m0   = w * 16;

    int ib  = blockIdx.x;
    int bh  = blockIdx.y;
    int b   = bh / NHh, h = bh % NHh;
    int rowbase = b * Tt + ib * 64;
    int qo2 = h * (HSz / 2);
    int ko2 = CU + qo2;
    int vo2 = 2 * CU + qo2;

    const float NEG_INF = __int_as_float(0xff800000);

    // ---- load Q tile (64 rows x 32 u32) ----
    #pragma unroll
    for (int i = 0; i < 4; i++) {
        int id = tid + i * 128;          // 0..511 uint4s
        int r  = id >> 3;
        int c4 = (id & 7) << 2;
        uint4 v = *(const uint4*)(qkv + (size_t)(rowbase + r) * QKVU + qo2 + c4);
        *(uint4*)(sQ + r * AQS + c4) = v;
    }
    __syncthreads();

    // ---- hoist Q fragments (warp-local rows) ----
    uint32_t aq[4][4];
    #pragma unroll
    for (int ks = 0; ks < 4; ks++) {
        const uint32_t* p = sQ + (m0 + g) * AQS + ks * 8 + q;
        aq[ks][0] = p[0];
        aq[ks][1] = p[8 * AQS];
        aq[ks][2] = p[4];
        aq[ks][3] = p[8 * AQS + 4];
    }
    uint32_t* sP = sPa + w * 16 * APS;

    float mA = NEG_INF, mB = NEG_INF, lA = 0.f, lB = 0.f;
    float o[8][4];
    #pragma unroll
    for (int nt = 0; nt < 8; nt++)
        #pragma unroll
        for (int r = 0; r < 4; r++) o[nt][r] = 0.f;

    const float scale = 0.03608439182435161f;   // 768^-0.5 (C, not hs)

    for (int jb = 0; jb <= ib; jb++) {
        if (jb) __syncthreads();
        int krow = b * Tt + jb * 64;
        // ---- K -> sKt[dpair][j] (transpose) ----
        #pragma unroll
        for (int i = 0; i < 4; i++) {
            int id = tid + i * 128;       // 0..511
            int r  = id & 63;             // row j
            int c4 = (id >> 6) << 2;      // dpair 0,4,..,28
            uint4 kv = *(const uint4*)(qkv + (size_t)(krow + r) * QKVU + ko2 + c4);
            sKt[(c4 + 0) * AKS + r] = kv.x;
            sKt[(c4 + 1) * AKS + r] = kv.y;
            sKt[(c4 + 2) * AKS + r] = kv.z;
            sKt[(c4 + 3) * AKS + r] = kv.w;
        }
        // ---- V -> sV[jpair][d half-col] (pair-pack along j) ----
        #pragma unroll
        for (int i = 0; i < 8; i++) {
            int id = tid + i * 128;       // 0..1023
            int jp = id >> 5;             // 0..31
            int dd = id & 31;             // dpair 0..31
            uint32_t x = qkv[(size_t)(krow + 2 * jp)     * QKVU + vo2 + dd];
            uint32_t y = qkv[(size_t)(krow + 2 * jp + 1) * QKVU + vo2 + dd];
            sV[jp * AKS + 2 * dd]     = __byte_perm(x, y, 0x5410);
            sV[jp * AKS + 2 * dd + 1] = __byte_perm(x, y, 0x7632);
        }
        __syncthreads();

        // ---- S = Q K^T ----
        float sacc[8][4];
        #pragma unroll
        for (int nt = 0; nt < 8; nt++)
            #pragma unroll
            for (int r = 0; r < 4; r++) sacc[nt][r] = 0.f;

        #pragma unroll
        for (int ks = 0; ks < 4; ks++) {
            int kk = ks * 8 + q;
            #pragma unroll
            for (int nt = 0; nt < 8; nt++) {
                uint32_t b0 = sKt[kk * AKS + nt * 8 + g];
                uint32_t b1 = sKt[(kk + 4) * AKS + nt * 8 + g];
                mma_f16(sacc[nt], aq[ks][0], aq[ks][1], aq[ks][2], aq[ks][3], b0, b1);
            }
        }

        // ---- scale + causal mask ----
        bool diag = (jb == ib);
        #pragma unroll
        for (int nt = 0; nt < 8; nt++) {
            #pragma unroll
            for (int r = 0; r < 4; r++) {
                float v = sacc[nt][r] * scale;
                if (diag) {
                    int lrow = m0 + g + ((r >= 2) ? 8 : 0);
                    int lcol = nt * 8 + 2 * q + (r & 1);
                    if (lcol > lrow) v = NEG_INF;
                }
                sacc[nt][r] = v;
            }
        }

        // ---- online softmax ----
        float bmaxA = NEG_INF, bmaxB = NEG_INF;
        #pragma unroll
        for (int nt = 0; nt < 8; nt++) {
            bmaxA = fmaxf(bmaxA, fmaxf(sacc[nt][0], sacc[nt][1]));
            bmaxB = fmaxf(bmaxB, fmaxf(sacc[nt][2], sacc[nt][3]));
        }
        #pragma unroll
        for (int off = 1; off < 4; off <<= 1) {
            bmaxA = fmaxf(bmaxA, __shfl_xor_sync(0xffffffffu, bmaxA, off));
            bmaxB = fmaxf(bmaxB, __shfl_xor_sync(0xffffffffu, bmaxB, off));
        }
        float mnA = fmaxf(mA, bmaxA), mnB = fmaxf(mB, bmaxB);
        float sumA = 0.f, sumB = 0.f;
        #pragma unroll
        for (int nt = 0; nt < 8; nt++) {
            float p0 = __expf(sacc[nt][0] - mnA);
            float p1 = __expf(sacc[nt][1] - mnA);
            float p2 = __expf(sacc[nt][2] - mnB);
            float p3 = __expf(sacc[nt][3] - mnB);
            sumA += p0 + p1; sumB += p2 + p3;
            sacc[nt][0] = p0; sacc[nt][1] = p1;
            sacc[nt][2] = p2; sacc[nt][3] = p3;
        }
        #pragma unroll
        for (int off = 1; off < 4; off <<= 1) {
            sumA += __shfl_xor_sync(0xffffffffu, sumA, off);
            sumB += __shfl_xor_sync(0xffffffffu, sumB, off);
        }
        float alphaA = __expf(mA - mnA), alphaB = __expf(mB - mnB);
        lA = lA * alphaA + sumA; lB = lB * alphaB + sumB;
        mA = mnA; mB = mnB;
        #pragma unroll
        for (int nt = 0; nt < 8; nt++) {
            o[nt][0] *= alphaA; o[nt][1] *= alphaA;
            o[nt][2] *= alphaB; o[nt][3] *= alphaB;
        }

        // ---- P (half2 pairs) -> warp-local sP[row][jpair] ----
        #pragma unroll
        for (int nt = 0; nt < 8; nt++) {
            sP[g * APS + nt * 4 + q]       = f2h2(sacc[nt][0], sacc[nt][1]);
            sP[(g + 8) * APS + nt * 4 + q] = f2h2(sacc[nt][2], sacc[nt][3]);
        }
        __syncwarp();

        // ---- O += P V ----
        #pragma unroll
        for (int ks = 0; ks < 4; ks++) {
            int kk = ks * 8 + q;
            const uint32_t* pp = sP + g * APS + kk;
            uint32_t a0 = pp[0];
            uint32_t a1 = pp[8 * APS];
            uint32_t a2 = pp[4];
            uint32_t a3 = pp[8 * APS + 4];
            #pragma unroll
            for (int nt = 0; nt < 8; nt++) {
                uint32_t b0 = sV[kk * AKS + nt * 8 + g];
                uint32_t b1 = sV[(kk + 4) * AKS + nt * 8 + g];
                mma_f16(o[nt], a0, a1, a2, a3, b0, b1);
            }
        }
        __syncwarp();
    }

    // ---- epilogue: normalize, store half2 ----
    float invA = 1.0f / lA, invB = 1.0f / lB;
    #pragma unroll
    for (int nt = 0; nt < 8; nt++) {
        int colp = h * (HSz / 2) + nt * 4 + q;   // u32 column
        int rA = rowbase + m0 + g;
        int rB = rA + 8;
        O[(size_t)rA * CU + colp] = f2h2(o[nt][0] * invA, o[nt][1] * invA);
        O[(size_t)rB * CU + colp] = f2h2(o[nt][2] * invB, o[nt][3] * invB);
    }
}

// ---------------------------------------------------------------------------
// Launch
// ---------------------------------------------------------------------------
extern "C" void kernel_launch(void* const* d_in, const int* in_sizes, int n_in,
                              void* d_out, int out_size)
{
    const float* x   = (const float*)d_in[0];
    const float* Wq  = (const float*)d_in[1];
    const float* Wk  = (const float*)d_in[2];
    const float* Wv  = (const float*)d_in[3];
    const float* Wo  = (const float*)d_in[4];
    const float* bo  = (const float*)d_in[5];
    const float* W1  = (const float*)d_in[6];
    const float* b1  = (const float*)d_in[7];
    const float* W2  = (const float*)d_in[8];
    const float* b2  = (const float*)d_in[9];
    const float* g1  = (const float*)d_in[10];
    const float* be1 = (const float*)d_in[11];
    const float* g2  = (const float*)d_in[12];
    const float* be2 = (const float*)d_in[13];
    float* out = (float*)d_out;

    uint32_t *h, *qkv, *o, *h2, *ff, *wqkv, *wo, *w1, *w2;
    float *x2;
    cudaGetSymbolAddress((void**)&h,    g_h);
    cudaGetSymbolAddress((void**)&qkv,  g_qkv);
    cudaGetSymbolAddress((void**)&o,    g_o);
    cudaGetSymbolAddress((void**)&x2,   g_x2);
    cudaGetSymbolAddress((void**)&h2,   g_h2);
    cudaGetSymbolAddress((void**)&ff,   g_ff);
    cudaGetSymbolAddress((void**)&wqkv, g_wqkv);
    cudaGetSymbolAddress((void**)&wo,   g_wo);
    cudaGetSymbolAddress((void**)&w1,   g_w1);
    cudaGetSymbolAddress((void**)&w2,   g_w2);

    cudaFuncSetAttribute(gemm_tc<0,1>,
        cudaFuncAttributeMaxDynamicSharedMemorySize, GEMM_SMEM);
    cudaFuncSetAttribute(gemm_tc<1,0>,
        cudaFuncAttributeMaxDynamicSharedMemorySize, GEMM_SMEM);
    cudaFuncSetAttribute(gemm_tc<2,1>,
        cudaFuncAttributeMaxDynamicSharedMemorySize, GEMM_SMEM);

    dim3 blk(256);
    dim3 g768 (Cc   / 128, MR / 128);   // (6, 64)
    dim3 gqkv (QKVN / 128, MR / 128);   // (18, 64)
    dim3 g3072(FFd  / 128, MR / 128);   // (24, 64)

    // ---- weight conversion fp32 -> packed half2 k-pairs ----
    int tCC = CU * Cc;     // 294912
    int tCF = CU * FFd;    // 1179648
    int tFC = FFU * Cc;    // 1179648
    cvt_pack_kernel<<<(tCC + 255) / 256, blk>>>(Wq, wqkv, Cc, QKVN, 0,      tCC);
    cvt_pack_kernel<<<(tCC + 255) / 256, blk>>>(Wk, wqkv, Cc, QKVN, Cc,     tCC);
    cvt_pack_kernel<<<(tCC + 255) / 256, blk>>>(Wv, wqkv, Cc, QKVN, 2 * Cc, tCC);
    cvt_pack_kernel<<<(tCC + 255) / 256, blk>>>(Wo, wo,   Cc, Cc,   0,      tCC);
    cvt_pack_kernel<<<(tCF + 255) / 256, blk>>>(W1, w1,   FFd, FFd, 0,      tCF);
    cvt_pack_kernel<<<(tFC + 255) / 256, blk>>>(W2, w2,   Cc,  Cc,  0,      tFC);

    // h = LN(x) (fp16)
    ln_kernel<<<MR, blk>>>(x, g1, be1, h);
    // qkv = h @ [Wq|Wk|Wv]  (fp16 out)
    gemm_tc<0,1><<<gqkv, blk, GEMM_SMEM>>>(h, wqkv, nullptr, nullptr, qkv, MR, QKVN, CU);
    // causal attention (fp16 out)
    attn_kernel<<<dim3(Tt / 64, Bb * NHh), dim3(128)>>>(qkv, o);
    // x2 = x + o @ Wo + bo (fp32 out)
    gemm_tc<1,0><<<g768, blk, GEMM_SMEM>>>(o, wo, bo, x, x2, MR, Cc, CU);
    // h2 = LN(x2) (fp16)
    ln_kernel<<<MR, blk>>>(x2, g2, be2, h2);
    // ff = gelu(h2 @ W1 + b1) (fp16 out)
    gemm_tc<2,1><<<g3072, blk, GEMM_SMEM>>>(h2, w1, b1, nullptr, ff, MR, FFd, CU);
    // out = x2 + ff @ W2 + b2 (fp32 out)
    gemm_tc<1,0><<<g768, blk, GEMM_SMEM>>>(ff, w2, b2, x2, out, MR, Cc, FFU);
}